// round 3
// baseline (speedup 1.0000x reference)
#include <cuda_runtime.h>
#include <cstdint>

#define NMAX 50000
#define EMAX 800000

// ---------------- device scratch (no allocations allowed) ----------------
__device__ __align__(16) int   g_cnt[NMAX];
__device__ __align__(16) int   g_rowptr[NMAX];
__device__ __align__(16) int   g_cursor[NMAX];
__device__ __align__(16) float g_dinv[NMAX];
__device__ __align__(16) int2  g_ew[EMAX];           // {src, bitcast(norm)}
__device__ __align__(16) float g_bufA[NMAX * 64];
__device__ __align__(16) float g_bufB[NMAX * 64];
__device__ __align__(16) float g_bufC[NMAX * 64];

__device__ __forceinline__ float* bufptr(int s) {
    return (s == 0) ? g_bufA : ((s == 1) ? g_bufB : g_bufC);
}

// ---------------- CSR build ----------------
__global__ void k_zero(int n) {
    int i = blockIdx.x * blockDim.x + threadIdx.x;
    if (i < n) g_cnt[i] = 0;
}

__global__ void k_hist(const int* __restrict__ ei, int E, int n) {
    int i = blockIdx.x * blockDim.x + threadIdx.x;
    if (i < E) {
        int d = ei[E + i];
        if ((unsigned)d < (unsigned)n) atomicAdd(&g_cnt[d], 1);
    }
}

// single block, 1024 threads: exclusive scan of g_cnt -> g_rowptr/g_cursor, dinv
__global__ void k_scan(int n) {
    __shared__ int ss[1024];
    const int t = threadIdx.x;
    const int chunk = (n + 1023) / 1024;
    const int start = t * chunk;
    const int end = min(start + chunk, n);
    int s = 0;
    for (int i = start; i < end; i++) s += g_cnt[i];
    ss[t] = s;
    __syncthreads();
    for (int off = 1; off < 1024; off <<= 1) {
        int v = (t >= off) ? ss[t - off] : 0;
        __syncthreads();
        ss[t] += v;
        __syncthreads();
    }
    int run = ss[t] - s;  // exclusive prefix
    for (int i = start; i < end; i++) {
        int c = g_cnt[i];
        g_rowptr[i] = run;
        g_cursor[i] = run;
        g_dinv[i] = rsqrtf((float)(c + 1));  // +1 self loop
        run += c;
    }
}

__global__ void k_scatter(const int* __restrict__ ei, int E, int n) {
    int i = blockIdx.x * blockDim.x + threadIdx.x;
    if (i < E) {
        int s = ei[i];
        int d = ei[E + i];
        if ((unsigned)s < (unsigned)n && (unsigned)d < (unsigned)n) {
            int pos = atomicAdd(&g_cursor[d], 1);
            g_ew[pos] = make_int2(s, __float_as_int(g_dinv[s] * g_dinv[d]));
        }
    }
}

// ---------------- dual-output GEMM: [outA|outB] = X @ [Wa|Wb] ----------------
// X: n x K row-major. Wa/Wb: K x (NC/2). Static smem, K chunked by 32.
template <int K, int NC>
__global__ __launch_bounds__(256) void k_gemm_dual(
    const float* __restrict__ Xext, int xsel,
    const float* __restrict__ Wa, const float* __restrict__ Wb,
    int oselA, int oselB, int n)
{
    constexpr int RB = 64;
    constexpr int KC = 32;
    constexpr int HALF = NC / 2;
    constexpr int CG = NC / 4;            // 4-col groups
    constexpr int RPT = RB / (256 / CG);  // rows per thread

    __shared__ __align__(16) float Wsm[KC][NC];
    __shared__ __align__(16) float Xsm[RB][KC];

    const float* X = (xsel >= 0) ? bufptr(xsel) : Xext;
    float* outA = bufptr(oselA);
    float* outB = bufptr(oselB);

    const int t = threadIdx.x;
    const int row0 = blockIdx.x * RB;
    const int tx = t % CG;
    const int ty = t / CG;

    float acc[RPT][4];
#pragma unroll
    for (int r = 0; r < RPT; r++) { acc[r][0] = acc[r][1] = acc[r][2] = acc[r][3] = 0.f; }

    for (int kc = 0; kc < K; kc += KC) {
        // load W chunk (both halves interleaved into NC columns)
        for (int idx = t; idx < KC * HALF; idx += 256) {
            int k = idx / HALF, j = idx % HALF;
            Wsm[k][j]        = Wa[(size_t)(kc + k) * HALF + j];
            Wsm[k][HALF + j] = Wb[(size_t)(kc + k) * HALF + j];
        }
        // load X chunk
        for (int idx = t; idx < RB * (KC / 4); idx += 256) {
            int r  = idx / (KC / 4);
            int c4 = (idx % (KC / 4)) * 4;
            float4 v = make_float4(0.f, 0.f, 0.f, 0.f);
            int row = row0 + r;
            if (row < n) v = *reinterpret_cast<const float4*>(X + (size_t)row * K + kc + c4);
            *reinterpret_cast<float4*>(&Xsm[r][c4]) = v;
        }
        __syncthreads();

#pragma unroll
        for (int k = 0; k < KC; k++) {
            float4 w = *reinterpret_cast<const float4*>(&Wsm[k][tx * 4]);
#pragma unroll
            for (int r = 0; r < RPT; r++) {
                float xv = Xsm[ty * RPT + r][k];
                acc[r][0] = fmaf(xv, w.x, acc[r][0]);
                acc[r][1] = fmaf(xv, w.y, acc[r][1]);
                acc[r][2] = fmaf(xv, w.z, acc[r][2]);
                acc[r][3] = fmaf(xv, w.w, acc[r][3]);
            }
        }
        __syncthreads();
    }

    const int c = tx * 4;
#pragma unroll
    for (int r = 0; r < RPT; r++) {
        int row = row0 + ty * RPT + r;
        if (row < n) {
            float4 v = make_float4(acc[r][0], acc[r][1], acc[r][2], acc[r][3]);
            if (c < HALF)
                *reinterpret_cast<float4*>(outA + (size_t)row * HALF + c) = v;
            else
                *reinterpret_cast<float4*>(outB + (size_t)row * HALF + (c - HALF)) = v;
        }
    }
}

// ---------------- propagation: out = A_hat @ h  (+ fused epilogue) ----------------
// warp per node. RELUB=false: out = acc + other[node,:] ; RELUB=true: out = relu(acc + bias)
template <int C, bool RELUB>
__global__ __launch_bounds__(256) void k_prop(
    int hsel, const float* __restrict__ bias, int othersel, int outsel, int n)
{
    constexpr int V = C / 32;  // floats per lane (2 or 1)
    const int wid = (blockIdx.x * blockDim.x + threadIdx.x) >> 5;
    const int lane = threadIdx.x & 31;
    if (wid >= n) return;

    const float* h = bufptr(hsel);
    float* out = bufptr(outsel);

    const float dv = g_dinv[wid];
    const float sw = dv * dv;
    const int rs = g_rowptr[wid];
    const int re = rs + g_cnt[wid];

    float a0, a1 = 0.f;
    if (V == 2) {
        float2 s = *reinterpret_cast<const float2*>(h + (size_t)wid * C + lane * 2);
        a0 = sw * s.x; a1 = sw * s.y;
    } else {
        a0 = sw * h[(size_t)wid * C + lane];
    }

    int e = rs;
    for (; e + 4 <= re; e += 4) {
        int2 w0 = g_ew[e], w1 = g_ew[e + 1], w2 = g_ew[e + 2], w3 = g_ew[e + 3];
        if (V == 2) {
            float2 h0 = *reinterpret_cast<const float2*>(h + (size_t)w0.x * C + lane * 2);
            float2 h1 = *reinterpret_cast<const float2*>(h + (size_t)w1.x * C + lane * 2);
            float2 h2 = *reinterpret_cast<const float2*>(h + (size_t)w2.x * C + lane * 2);
            float2 h3 = *reinterpret_cast<const float2*>(h + (size_t)w3.x * C + lane * 2);
            a0 = fmaf(__int_as_float(w0.y), h0.x, a0); a1 = fmaf(__int_as_float(w0.y), h0.y, a1);
            a0 = fmaf(__int_as_float(w1.y), h1.x, a0); a1 = fmaf(__int_as_float(w1.y), h1.y, a1);
            a0 = fmaf(__int_as_float(w2.y), h2.x, a0); a1 = fmaf(__int_as_float(w2.y), h2.y, a1);
            a0 = fmaf(__int_as_float(w3.y), h3.x, a0); a1 = fmaf(__int_as_float(w3.y), h3.y, a1);
        } else {
            float h0 = h[(size_t)w0.x * C + lane];
            float h1 = h[(size_t)w1.x * C + lane];
            float h2 = h[(size_t)w2.x * C + lane];
            float h3 = h[(size_t)w3.x * C + lane];
            a0 = fmaf(__int_as_float(w0.y), h0, a0);
            a0 = fmaf(__int_as_float(w1.y), h1, a0);
            a0 = fmaf(__int_as_float(w2.y), h2, a0);
            a0 = fmaf(__int_as_float(w3.y), h3, a0);
        }
    }
    for (; e < re; e++) {
        int2 we = g_ew[e];
        float wv = __int_as_float(we.y);
        if (V == 2) {
            float2 hv = *reinterpret_cast<const float2*>(h + (size_t)we.x * C + lane * 2);
            a0 = fmaf(wv, hv.x, a0); a1 = fmaf(wv, hv.y, a1);
        } else {
            a0 = fmaf(wv, h[(size_t)we.x * C + lane], a0);
        }
    }

    if (RELUB) {
        if (V == 2) {
            a0 = fmaxf(a0 + bias[lane * 2], 0.f);
            a1 = fmaxf(a1 + bias[lane * 2 + 1], 0.f);
        } else {
            a0 = fmaxf(a0 + bias[lane], 0.f);
        }
    } else {
        const float* other = bufptr(othersel);
        if (V == 2) {
            float2 o = *reinterpret_cast<const float2*>(other + (size_t)wid * C + lane * 2);
            a0 += o.x; a1 += o.y;
        } else {
            a0 += other[(size_t)wid * C + lane];
        }
    }

    if (V == 2)
        *reinterpret_cast<float2*>(out + (size_t)wid * C + lane * 2) = make_float2(a0, a1);
    else
        out[(size_t)wid * C + lane] = a0;
}

// ---------------- fused heads: z + coordinates ----------------
__global__ __launch_bounds__(256) void k_heads(
    int h2sel,
    const float* __restrict__ Wp1, const float* __restrict__ bp1,
    const float* __restrict__ Wp2, const float* __restrict__ bp2,
    const float* __restrict__ Wc1, const float* __restrict__ bc1,
    const float* __restrict__ Wc2, const float* __restrict__ bc2,
    float* __restrict__ out, int n)
{
    __shared__ float sWp1[32 * 32], sWp2[32 * 32], sWc1[32 * 16], sWc2[16 * 2];
    __shared__ float sbp1[32], sbp2[32], sbc1[16], sbc2[2];
    const int t = threadIdx.x;
    for (int i = t; i < 1024; i += 256) { sWp1[i] = Wp1[i]; sWp2[i] = Wp2[i]; }
    for (int i = t; i < 512; i += 256) sWc1[i] = Wc1[i];
    if (t < 32) { sWc2[t] = Wc2[t]; sbp1[t] = bp1[t]; sbp2[t] = bp2[t]; }
    if (t < 16) sbc1[t] = bc1[t];
    if (t < 2) sbc2[t] = bc2[t];
    __syncthreads();

    const float* h2 = bufptr(h2sel);
    const int wid = (blockIdx.x * blockDim.x + t) >> 5;
    const int lane = t & 31;
    if (wid >= n) return;

    const float hv = h2[(size_t)wid * 32 + lane];

    // t1 = relu(h2 @ Wp1 + bp1)
    float t1 = sbp1[lane];
#pragma unroll
    for (int k = 0; k < 32; k++)
        t1 = fmaf(__shfl_sync(0xffffffffu, hv, k), sWp1[k * 32 + lane], t1);
    t1 = fmaxf(t1, 0.f);

    // z = t1 @ Wp2 + bp2
    float z = sbp2[lane];
#pragma unroll
    for (int k = 0; k < 32; k++)
        z = fmaf(__shfl_sync(0xffffffffu, t1, k), sWp2[k * 32 + lane], z);
    out[(size_t)n * 2 + (size_t)wid * 32 + lane] = z;

    // tc = relu(h2 @ Wc1 + bc1)   (lanes use lane&15 slot)
    float tc = sbc1[lane & 15];
#pragma unroll
    for (int k = 0; k < 32; k++)
        tc = fmaf(__shfl_sync(0xffffffffu, hv, k), sWc1[k * 16 + (lane & 15)], tc);
    tc = fmaxf(tc, 0.f);

    // coords = tc @ Wc2 + bc2
    float c0 = 0.f, c1 = 0.f;
#pragma unroll
    for (int k = 0; k < 16; k++) {
        float v = __shfl_sync(0xffffffffu, tc, k);
        c0 = fmaf(v, sWc2[k * 2 + 0], c0);
        c1 = fmaf(v, sWc2[k * 2 + 1], c1);
    }
    if (lane == 0) {
        out[(size_t)wid * 2 + 0] = c0 + sbc2[0];
        out[(size_t)wid * 2 + 1] = c1 + sbc2[1];
    }
}

// ---------------- launch ----------------
extern "C" void kernel_launch(void* const* d_in, const int* in_sizes, int n_in,
                              void* d_out, int out_size)
{
    const float* x  = (const float*)d_in[0];
    const int*   ei = (const int*)d_in[1];      // int32! (jax x64 disabled)
    const float* W1_1 = (const float*)d_in[2];
    const float* W1_2 = (const float*)d_in[3];
    const float* b1   = (const float*)d_in[4];
    const float* W2_1 = (const float*)d_in[5];
    const float* W2_2 = (const float*)d_in[6];
    const float* b2   = (const float*)d_in[7];
    const float* Wp1  = (const float*)d_in[8];
    const float* bp1  = (const float*)d_in[9];
    const float* Wp2  = (const float*)d_in[10];
    const float* bp2  = (const float*)d_in[11];
    const float* Wc1  = (const float*)d_in[12];
    const float* bc1  = (const float*)d_in[13];
    const float* Wc2  = (const float*)d_in[14];
    const float* bc2  = (const float*)d_in[15];
    float* out = (float*)d_out;

    const int n = in_sizes[0] / 128;
    const int E = in_sizes[1] / 2;

    // CSR build
    k_zero   <<<(n + 255) / 256, 256>>>(n);
    k_hist   <<<(E + 255) / 256, 256>>>(ei, E, n);
    k_scan   <<<1, 1024>>>(n);
    k_scatter<<<(E + 255) / 256, 256>>>(ei, E, n);

    const int gb1 = (n + 63) / 64;
    const int pb  = (n + 7) / 8;  // 8 warps (nodes) per 256-thread block

    // layer 1: u = x@W1_1 (A), v = x@W1_2 (B); h1 = relu(P(u + P(v)) + b1)
    k_gemm_dual<128, 128><<<gb1, 256>>>(x, -1, W1_1, W1_2, 0, 1, n);
    k_prop<64, false><<<pb, 256>>>(1, nullptr, 0, 2, n);  // C = P(B) + A
    k_prop<64, true ><<<pb, 256>>>(2, b1, -1, 0, n);      // A = relu(P(C)+b1) = h1

    // layer 2: u2 = h1@W2_1 (B), v2 = h1@W2_2 (C)
    k_gemm_dual<64, 64><<<gb1, 256>>>(nullptr, 0, W2_1, W2_2, 1, 2, n);
    k_prop<32, false><<<pb, 256>>>(2, nullptr, 1, 0, n);  // A = P(C) + B
    k_prop<32, true ><<<pb, 256>>>(0, b2, -1, 1, n);      // B = relu(P(A)+b2) = h2

    // heads
    k_heads<<<pb, 256>>>(1, Wp1, bp1, Wp2, bp2, Wc1, bc1, Wc2, bc2, out, n);
}

// round 4
// speedup vs baseline: 1.0453x; 1.0453x over previous
#include <cuda_runtime.h>
#include <cstdint>

#define NMAX 50000
#define EMAX 800000

// ---------------- device scratch (no allocations allowed) ----------------
__device__ __align__(16) int   g_cnt[NMAX];
__device__ __align__(16) int   g_rowptr[NMAX];
__device__ __align__(16) int   g_cursor[NMAX];
__device__ __align__(16) float g_dinv[NMAX];
__device__ __align__(16) int2  g_ew[EMAX];           // {src, bitcast(norm)}
__device__ __align__(16) float g_bufA[NMAX * 64];
__device__ __align__(16) float g_bufB[NMAX * 64];
__device__ __align__(16) float g_bufC[NMAX * 64];

__device__ __forceinline__ float* bufptr(int s) {
    return (s == 0) ? g_bufA : ((s == 1) ? g_bufB : g_bufC);
}

// ---------------- CSR build ----------------
__global__ void k_zero(int n4) {
    int i = blockIdx.x * blockDim.x + threadIdx.x;
    if (i < n4) reinterpret_cast<int4*>(g_cnt)[i] = make_int4(0, 0, 0, 0);
}

__global__ void k_hist(const int* __restrict__ ei, int E, int n) {
    int i = blockIdx.x * blockDim.x + threadIdx.x;
    if (i < E) {
        int d = ei[E + i];
        if ((unsigned)d < (unsigned)n) atomicAdd(&g_cnt[d], 1);
    }
}

// single block, 1024 threads: exclusive scan of g_cnt -> g_rowptr/g_cursor, dinv
__global__ void k_scan(int n) {
    __shared__ int ss[1024];
    const int t = threadIdx.x;
    const int chunk = (n + 1023) / 1024;
    const int start = t * chunk;
    const int end = min(start + chunk, n);
    int s = 0;
    for (int i = start; i < end; i++) s += g_cnt[i];
    ss[t] = s;
    __syncthreads();
    for (int off = 1; off < 1024; off <<= 1) {
        int v = (t >= off) ? ss[t - off] : 0;
        __syncthreads();
        ss[t] += v;
        __syncthreads();
    }
    int run = ss[t] - s;  // exclusive prefix
    for (int i = start; i < end; i++) {
        int c = g_cnt[i];
        g_rowptr[i] = run;
        g_cursor[i] = run;
        g_dinv[i] = rsqrtf((float)(c + 1));  // +1 self loop
        run += c;
    }
}

__global__ void k_scatter(const int* __restrict__ ei, int E, int n) {
    int i = blockIdx.x * blockDim.x + threadIdx.x;
    if (i < E) {
        int s = ei[i];
        int d = ei[E + i];
        if ((unsigned)s < (unsigned)n && (unsigned)d < (unsigned)n) {
            int pos = atomicAdd(&g_cursor[d], 1);
            g_ew[pos] = make_int2(s, __float_as_int(g_dinv[s] * g_dinv[d]));
        }
    }
}

// ---------------- dual-output GEMM: [outA|outB] = X @ [Wa|Wb] ----------------
template <int K, int NC>
__global__ __launch_bounds__(256) void k_gemm_dual(
    const float* __restrict__ Xext, int xsel,
    const float* __restrict__ Wa, const float* __restrict__ Wb,
    int oselA, int oselB, int n)
{
    constexpr int RB = 64;
    constexpr int KC = 32;
    constexpr int HALF = NC / 2;
    constexpr int CG = NC / 4;
    constexpr int RPT = RB / (256 / CG);

    __shared__ __align__(16) float Wsm[KC][NC];
    __shared__ __align__(16) float Xsm[RB][KC];

    const float* X = (xsel >= 0) ? bufptr(xsel) : Xext;
    float* outA = bufptr(oselA);
    float* outB = bufptr(oselB);

    const int t = threadIdx.x;
    const int row0 = blockIdx.x * RB;
    const int tx = t % CG;
    const int ty = t / CG;

    float acc[RPT][4];
#pragma unroll
    for (int r = 0; r < RPT; r++) { acc[r][0] = acc[r][1] = acc[r][2] = acc[r][3] = 0.f; }

    for (int kc = 0; kc < K; kc += KC) {
        for (int idx = t; idx < KC * HALF; idx += 256) {
            int k = idx / HALF, j = idx % HALF;
            Wsm[k][j]        = Wa[(size_t)(kc + k) * HALF + j];
            Wsm[k][HALF + j] = Wb[(size_t)(kc + k) * HALF + j];
        }
        for (int idx = t; idx < RB * (KC / 4); idx += 256) {
            int r  = idx / (KC / 4);
            int c4 = (idx % (KC / 4)) * 4;
            float4 v = make_float4(0.f, 0.f, 0.f, 0.f);
            int row = row0 + r;
            if (row < n) v = *reinterpret_cast<const float4*>(X + (size_t)row * K + kc + c4);
            *reinterpret_cast<float4*>(&Xsm[r][c4]) = v;
        }
        __syncthreads();

#pragma unroll
        for (int k = 0; k < KC; k++) {
            float4 w = *reinterpret_cast<const float4*>(&Wsm[k][tx * 4]);
#pragma unroll
            for (int r = 0; r < RPT; r++) {
                float xv = Xsm[ty * RPT + r][k];
                acc[r][0] = fmaf(xv, w.x, acc[r][0]);
                acc[r][1] = fmaf(xv, w.y, acc[r][1]);
                acc[r][2] = fmaf(xv, w.z, acc[r][2]);
                acc[r][3] = fmaf(xv, w.w, acc[r][3]);
            }
        }
        __syncthreads();
    }

    const int c = tx * 4;
#pragma unroll
    for (int r = 0; r < RPT; r++) {
        int row = row0 + ty * RPT + r;
        if (row < n) {
            float4 v = make_float4(acc[r][0], acc[r][1], acc[r][2], acc[r][3]);
            if (c < HALF)
                *reinterpret_cast<float4*>(outA + (size_t)row * HALF + c) = v;
            else
                *reinterpret_cast<float4*>(outB + (size_t)row * HALF + (c - HALF)) = v;
        }
    }
}

// ---------------- propagation, float4 lanes ----------------
// C channels, L = C/4 lanes per node. RELUB selects epilogue.
template <int C, bool RELUB>
__global__ __launch_bounds__(256) void k_prop(
    int hsel, const float* __restrict__ bias, int othersel, int outsel, int n)
{
    constexpr int L = C / 4;                    // lanes per node (16 or 8)
    const int tid = blockIdx.x * blockDim.x + threadIdx.x;
    const int node = tid / L;
    const int l = threadIdx.x & (L - 1);
    if (node >= n) return;

    const float* h = bufptr(hsel);
    float* out = bufptr(outsel);

    const float dv = g_dinv[node];
    const float sw = dv * dv;
    const int rs = g_rowptr[node];
    const int re = rs + g_cnt[node];

    float4 s = *reinterpret_cast<const float4*>(h + (size_t)node * C + l * 4);
    float4 a = make_float4(sw * s.x, sw * s.y, sw * s.z, sw * s.w);

    int e = rs;
    for (; e + 4 <= re; e += 4) {
        int2 w0 = g_ew[e], w1 = g_ew[e + 1], w2 = g_ew[e + 2], w3 = g_ew[e + 3];
        float4 h0 = *reinterpret_cast<const float4*>(h + (size_t)w0.x * C + l * 4);
        float4 h1 = *reinterpret_cast<const float4*>(h + (size_t)w1.x * C + l * 4);
        float4 h2 = *reinterpret_cast<const float4*>(h + (size_t)w2.x * C + l * 4);
        float4 h3 = *reinterpret_cast<const float4*>(h + (size_t)w3.x * C + l * 4);
        float f0 = __int_as_float(w0.y), f1 = __int_as_float(w1.y);
        float f2 = __int_as_float(w2.y), f3 = __int_as_float(w3.y);
        a.x = fmaf(f0, h0.x, a.x); a.y = fmaf(f0, h0.y, a.y);
        a.z = fmaf(f0, h0.z, a.z); a.w = fmaf(f0, h0.w, a.w);
        a.x = fmaf(f1, h1.x, a.x); a.y = fmaf(f1, h1.y, a.y);
        a.z = fmaf(f1, h1.z, a.z); a.w = fmaf(f1, h1.w, a.w);
        a.x = fmaf(f2, h2.x, a.x); a.y = fmaf(f2, h2.y, a.y);
        a.z = fmaf(f2, h2.z, a.z); a.w = fmaf(f2, h2.w, a.w);
        a.x = fmaf(f3, h3.x, a.x); a.y = fmaf(f3, h3.y, a.y);
        a.z = fmaf(f3, h3.z, a.z); a.w = fmaf(f3, h3.w, a.w);
    }
    for (; e < re; e++) {
        int2 we = g_ew[e];
        float wv = __int_as_float(we.y);
        float4 hv = *reinterpret_cast<const float4*>(h + (size_t)we.x * C + l * 4);
        a.x = fmaf(wv, hv.x, a.x); a.y = fmaf(wv, hv.y, a.y);
        a.z = fmaf(wv, hv.z, a.z); a.w = fmaf(wv, hv.w, a.w);
    }

    if (RELUB) {
        const float4 b = *reinterpret_cast<const float4*>(bias + l * 4);
        a.x = fmaxf(a.x + b.x, 0.f); a.y = fmaxf(a.y + b.y, 0.f);
        a.z = fmaxf(a.z + b.z, 0.f); a.w = fmaxf(a.w + b.w, 0.f);
    } else {
        const float* other = bufptr(othersel);
        float4 o = *reinterpret_cast<const float4*>(other + (size_t)node * C + l * 4);
        a.x += o.x; a.y += o.y; a.z += o.z; a.w += o.w;
    }
    *reinterpret_cast<float4*>(out + (size_t)node * C + l * 4) = a;
}

// ---------------- fused: h2 = relu(P(A)+b2) -> heads -> out ----------------
// warp per node; lane = channel (32 channels).
__global__ __launch_bounds__(256) void k_prop_heads(
    int hsel, const float* __restrict__ b2,
    const float* __restrict__ Wp1, const float* __restrict__ bp1,
    const float* __restrict__ Wp2, const float* __restrict__ bp2,
    const float* __restrict__ Wc1, const float* __restrict__ bc1,
    const float* __restrict__ Wc2, const float* __restrict__ bc2,
    float* __restrict__ out, int n)
{
    __shared__ float sWp1[32 * 32], sWp2[32 * 32], sWc1[32 * 16], sWc2[16 * 2];
    __shared__ float sbp1[32], sbp2[32], sbc1[16], sbc2[2];
    const int t = threadIdx.x;
    for (int i = t; i < 1024; i += 256) { sWp1[i] = Wp1[i]; sWp2[i] = Wp2[i]; }
    for (int i = t; i < 512; i += 256) sWc1[i] = Wc1[i];
    if (t < 32) { sWc2[t] = Wc2[t]; sbp1[t] = bp1[t]; sbp2[t] = bp2[t]; }
    if (t < 16) sbc1[t] = bc1[t];
    if (t < 2) sbc2[t] = bc2[t];
    __syncthreads();

    const float* h = bufptr(hsel);
    const int node = (blockIdx.x * blockDim.x + t) >> 5;
    const int lane = t & 31;
    if (node >= n) return;

    // ---- propagation for 32 channels, one per lane ----
    const float dv = g_dinv[node];
    const float sw = dv * dv;
    const int rs = g_rowptr[node];
    const int re = rs + g_cnt[node];

    float acc = sw * h[(size_t)node * 32 + lane];
    int e = rs;
    for (; e + 4 <= re; e += 4) {
        int2 w0 = g_ew[e], w1 = g_ew[e + 1], w2 = g_ew[e + 2], w3 = g_ew[e + 3];
        float h0 = h[(size_t)w0.x * 32 + lane];
        float h1 = h[(size_t)w1.x * 32 + lane];
        float h2v = h[(size_t)w2.x * 32 + lane];
        float h3 = h[(size_t)w3.x * 32 + lane];
        acc = fmaf(__int_as_float(w0.y), h0, acc);
        acc = fmaf(__int_as_float(w1.y), h1, acc);
        acc = fmaf(__int_as_float(w2.y), h2v, acc);
        acc = fmaf(__int_as_float(w3.y), h3, acc);
    }
    for (; e < re; e++) {
        int2 we = g_ew[e];
        acc = fmaf(__int_as_float(we.y), h[(size_t)we.x * 32 + lane], acc);
    }
    const float hv = fmaxf(acc + b2[lane], 0.f);   // h2[node][lane]

    // ---- heads ----
    float t1 = sbp1[lane];
#pragma unroll
    for (int k = 0; k < 32; k++)
        t1 = fmaf(__shfl_sync(0xffffffffu, hv, k), sWp1[k * 32 + lane], t1);
    t1 = fmaxf(t1, 0.f);

    float z = sbp2[lane];
#pragma unroll
    for (int k = 0; k < 32; k++)
        z = fmaf(__shfl_sync(0xffffffffu, t1, k), sWp2[k * 32 + lane], z);
    out[(size_t)n * 2 + (size_t)node * 32 + lane] = z;

    float tc = sbc1[lane & 15];
#pragma unroll
    for (int k = 0; k < 32; k++)
        tc = fmaf(__shfl_sync(0xffffffffu, hv, k), sWc1[k * 16 + (lane & 15)], tc);
    tc = fmaxf(tc, 0.f);

    float c0 = 0.f, c1 = 0.f;
#pragma unroll
    for (int k = 0; k < 16; k++) {
        float v = __shfl_sync(0xffffffffu, tc, k);
        c0 = fmaf(v, sWc2[k * 2 + 0], c0);
        c1 = fmaf(v, sWc2[k * 2 + 1], c1);
    }
    if (lane == 0) {
        out[(size_t)node * 2 + 0] = c0 + sbc2[0];
        out[(size_t)node * 2 + 1] = c1 + sbc2[1];
    }
}

// ---------------- launch ----------------
extern "C" void kernel_launch(void* const* d_in, const int* in_sizes, int n_in,
                              void* d_out, int out_size)
{
    const float* x  = (const float*)d_in[0];
    const int*   ei = (const int*)d_in[1];      // int32 (jax x64 disabled)
    const float* W1_1 = (const float*)d_in[2];
    const float* W1_2 = (const float*)d_in[3];
    const float* b1   = (const float*)d_in[4];
    const float* W2_1 = (const float*)d_in[5];
    const float* W2_2 = (const float*)d_in[6];
    const float* b2   = (const float*)d_in[7];
    const float* Wp1  = (const float*)d_in[8];
    const float* bp1  = (const float*)d_in[9];
    const float* Wp2  = (const float*)d_in[10];
    const float* bp2  = (const float*)d_in[11];
    const float* Wc1  = (const float*)d_in[12];
    const float* bc1  = (const float*)d_in[13];
    const float* Wc2  = (const float*)d_in[14];
    const float* bc2  = (const float*)d_in[15];
    float* out = (float*)d_out;

    const int n = in_sizes[0] / 128;
    const int E = in_sizes[1] / 2;

    // CSR build
    const int n4 = (n + 3) / 4;
    k_zero   <<<(n4 + 255) / 256, 256>>>(n4);
    k_hist   <<<(E + 255) / 256, 256>>>(ei, E, n);
    k_scan   <<<1, 1024>>>(n);
    k_scatter<<<(E + 255) / 256, 256>>>(ei, E, n);

    const int gb1 = (n + 63) / 64;
    const int pb64 = (n * 16 + 255) / 256;   // 16 lanes/node
    const int pb32 = (n * 8 + 255) / 256;    // 8 lanes/node
    const int pbh  = (n + 7) / 8;            // warp/node

    // layer 1: u = x@W1_1 (A), v = x@W1_2 (B); h1 = relu(P(u + P(v)) + b1)
    k_gemm_dual<128, 128><<<gb1, 256>>>(x, -1, W1_1, W1_2, 0, 1, n);
    k_prop<64, false><<<pb64, 256>>>(1, nullptr, 0, 2, n);  // C = P(B) + A
    k_prop<64, true ><<<pb64, 256>>>(2, b1, -1, 0, n);      // A = relu(P(C)+b1) = h1

    // layer 2: u2 = h1@W2_1 (B), v2 = h1@W2_2 (C)
    k_gemm_dual<64, 64><<<gb1, 256>>>(nullptr, 0, W2_1, W2_2, 1, 2, n);
    k_prop<32, false><<<pb32, 256>>>(2, nullptr, 1, 0, n);  // A = P(C) + B

    // fused: h2 = relu(P(A)+b2) -> heads -> out
    k_prop_heads<<<pbh, 256>>>(0, b2, Wp1, bp1, Wp2, bp2, Wc1, bc1, Wc2, bc2, out, n);
}

// round 5
// speedup vs baseline: 1.0932x; 1.0459x over previous
#include <cuda_runtime.h>
#include <cstdint>

#define NMAX 50000
#define EMAX 800000

// ---------------- device scratch ----------------
__device__ __align__(16) int   g_cnt[NMAX];
__device__ __align__(16) int   g_rowptr[NMAX];
__device__ __align__(16) int   g_cursor[NMAX];
__device__ __align__(16) float g_dinv[NMAX];
__device__ __align__(16) int2  g_ew[EMAX];           // {src, bitcast(norm)}
__device__ __align__(16) float g_bufA[NMAX * 64];
__device__ __align__(16) float g_bufB[NMAX * 64];
__device__ __align__(16) float g_bufC[NMAX * 64];

__device__ __forceinline__ float* bufptr(int s) {
    return (s == 0) ? g_bufA : ((s == 1) ? g_bufB : g_bufC);
}

// ---------------- static streams/events (created before any checkpoint) ----------------
static cudaStream_t g_s1;
static cudaEvent_t  g_ef, g_ej;
static struct _StreamInit {
    _StreamInit() {
        cudaStreamCreateWithFlags(&g_s1, cudaStreamNonBlocking);
        cudaEventCreateWithFlags(&g_ef, cudaEventDisableTiming);
        cudaEventCreateWithFlags(&g_ej, cudaEventDisableTiming);
    }
} _stream_init;

// ---------------- CSR build ----------------
__global__ void k_zero(int n4) {
    int i = blockIdx.x * blockDim.x + threadIdx.x;
    if (i < n4) reinterpret_cast<int4*>(g_cnt)[i] = make_int4(0, 0, 0, 0);
}

__global__ void k_hist(const int* __restrict__ ei, int E, int n) {
    int i = blockIdx.x * blockDim.x + threadIdx.x;
    if (i < E) {
        int d = ei[E + i];
        if ((unsigned)d < (unsigned)n) atomicAdd(&g_cnt[d], 1);
    }
}

__global__ void k_scan(int n) {
    __shared__ int ss[1024];
    const int t = threadIdx.x;
    const int chunk = (n + 1023) / 1024;
    const int start = t * chunk;
    const int end = min(start + chunk, n);
    int s = 0;
    for (int i = start; i < end; i++) s += g_cnt[i];
    ss[t] = s;
    __syncthreads();
    for (int off = 1; off < 1024; off <<= 1) {
        int v = (t >= off) ? ss[t - off] : 0;
        __syncthreads();
        ss[t] += v;
        __syncthreads();
    }
    int run = ss[t] - s;
    for (int i = start; i < end; i++) {
        int c = g_cnt[i];
        g_rowptr[i] = run;
        g_cursor[i] = run;
        g_dinv[i] = rsqrtf((float)(c + 1));
        run += c;
    }
}

__global__ void k_scatter(const int* __restrict__ ei, int E, int n) {
    int i = blockIdx.x * blockDim.x + threadIdx.x;
    if (i < E) {
        int s = ei[i];
        int d = ei[E + i];
        if ((unsigned)s < (unsigned)n && (unsigned)d < (unsigned)n) {
            int pos = atomicAdd(&g_cursor[d], 1);
            g_ew[pos] = make_int2(s, __float_as_int(g_dinv[s] * g_dinv[d]));
        }
    }
}

// ---------------- dual-output GEMM: [outA|outB] = X @ [Wa|Wb] ----------------
// 128xNC block tile, 256 threads, 8-col x RPT-row micro-tile, X transposed in smem.
template <int K, int NC>
__global__ __launch_bounds__(256) void k_gemm_dual(
    const float* __restrict__ Xext, int xsel,
    const float* __restrict__ Wa, const float* __restrict__ Wb,
    int oselA, int oselB, int n)
{
    constexpr int RB  = 128;
    constexpr int KC  = 32;
    constexpr int RBP = RB + 4;
    constexpr int HALF = NC / 2;
    constexpr int TX  = NC / 8;        // 16 (NC=128) or 8 (NC=64)
    constexpr int TY  = 256 / TX;      // 16 or 32
    constexpr int RPT = RB / TY;       // 8 or 4

    __shared__ __align__(16) float Wsm[KC][NC];
    __shared__ __align__(16) float XsmT[KC][RBP];

    const float* X = (xsel >= 0) ? bufptr(xsel) : Xext;
    float* outA = bufptr(oselA);
    float* outB = bufptr(oselB);

    const int t = threadIdx.x;
    const int row0 = blockIdx.x * RB;
    const int tx = t % TX;
    const int ty = t / TX;

    float acc[RPT][8];
#pragma unroll
    for (int r = 0; r < RPT; r++)
#pragma unroll
        for (int c = 0; c < 8; c++) acc[r][c] = 0.f;

    for (int kc = 0; kc < K; kc += KC) {
        // W chunk: [Wa|Wb] side by side
        for (int idx = t; idx < KC * HALF; idx += 256) {
            int k = idx / HALF, j = idx % HALF;
            Wsm[k][j]        = Wa[(size_t)(kc + k) * HALF + j];
            Wsm[k][HALF + j] = Wb[(size_t)(kc + k) * HALF + j];
        }
        // X chunk, transposed into XsmT[k][r]
        for (int idx = t; idx < RB * (KC / 4); idx += 256) {
            int c4 = idx % (KC / 4);
            int r  = idx / (KC / 4);
            float4 v = make_float4(0.f, 0.f, 0.f, 0.f);
            int row = row0 + r;
            if (row < n) v = *reinterpret_cast<const float4*>(X + (size_t)row * K + kc + c4 * 4);
            XsmT[c4 * 4 + 0][r] = v.x;
            XsmT[c4 * 4 + 1][r] = v.y;
            XsmT[c4 * 4 + 2][r] = v.z;
            XsmT[c4 * 4 + 3][r] = v.w;
        }
        __syncthreads();

#pragma unroll
        for (int k = 0; k < KC; k++) {
            float w[8];
            *reinterpret_cast<float4*>(&w[0]) = *reinterpret_cast<const float4*>(&Wsm[k][tx * 8]);
            *reinterpret_cast<float4*>(&w[4]) = *reinterpret_cast<const float4*>(&Wsm[k][tx * 8 + 4]);
            float xr[RPT];
#pragma unroll
            for (int rr = 0; rr < RPT / 4; rr++)
                *reinterpret_cast<float4*>(&xr[rr * 4]) =
                    *reinterpret_cast<const float4*>(&XsmT[k][ty * RPT + rr * 4]);
#pragma unroll
            for (int r = 0; r < RPT; r++)
#pragma unroll
                for (int c = 0; c < 8; c++)
                    acc[r][c] = fmaf(xr[r], w[c], acc[r][c]);
        }
        __syncthreads();
    }

    const int c0 = tx * 8;
#pragma unroll
    for (int r = 0; r < RPT; r++) {
        int row = row0 + ty * RPT + r;
        if (row < n) {
            float4 v0 = make_float4(acc[r][0], acc[r][1], acc[r][2], acc[r][3]);
            float4 v1 = make_float4(acc[r][4], acc[r][5], acc[r][6], acc[r][7]);
            if (c0 < HALF) {
                *reinterpret_cast<float4*>(outA + (size_t)row * HALF + c0)     = v0;
                *reinterpret_cast<float4*>(outA + (size_t)row * HALF + c0 + 4) = v1;
            } else {
                *reinterpret_cast<float4*>(outB + (size_t)row * HALF + c0 - HALF)     = v0;
                *reinterpret_cast<float4*>(outB + (size_t)row * HALF + c0 - HALF + 4) = v1;
            }
        }
    }
}

// ---------------- propagation, float4 lanes ----------------
template <int C, bool RELUB>
__global__ __launch_bounds__(256) void k_prop(
    int hsel, const float* __restrict__ bias, int othersel, int outsel, int n)
{
    constexpr int L = C / 4;
    const int tid = blockIdx.x * blockDim.x + threadIdx.x;
    const int node = tid / L;
    const int l = threadIdx.x & (L - 1);
    if (node >= n) return;

    const float* h = bufptr(hsel);
    float* out = bufptr(outsel);

    const float dv = g_dinv[node];
    const float sw = dv * dv;
    const int rs = g_rowptr[node];
    const int re = rs + g_cnt[node];

    float4 s = *reinterpret_cast<const float4*>(h + (size_t)node * C + l * 4);
    float4 a = make_float4(sw * s.x, sw * s.y, sw * s.z, sw * s.w);

    int e = rs;
    for (; e + 4 <= re; e += 4) {
        int2 w0 = g_ew[e], w1 = g_ew[e + 1], w2 = g_ew[e + 2], w3 = g_ew[e + 3];
        float4 h0 = *reinterpret_cast<const float4*>(h + (size_t)w0.x * C + l * 4);
        float4 h1 = *reinterpret_cast<const float4*>(h + (size_t)w1.x * C + l * 4);
        float4 h2 = *reinterpret_cast<const float4*>(h + (size_t)w2.x * C + l * 4);
        float4 h3 = *reinterpret_cast<const float4*>(h + (size_t)w3.x * C + l * 4);
        float f0 = __int_as_float(w0.y), f1 = __int_as_float(w1.y);
        float f2 = __int_as_float(w2.y), f3 = __int_as_float(w3.y);
        a.x = fmaf(f0, h0.x, a.x); a.y = fmaf(f0, h0.y, a.y);
        a.z = fmaf(f0, h0.z, a.z); a.w = fmaf(f0, h0.w, a.w);
        a.x = fmaf(f1, h1.x, a.x); a.y = fmaf(f1, h1.y, a.y);
        a.z = fmaf(f1, h1.z, a.z); a.w = fmaf(f1, h1.w, a.w);
        a.x = fmaf(f2, h2.x, a.x); a.y = fmaf(f2, h2.y, a.y);
        a.z = fmaf(f2, h2.z, a.z); a.w = fmaf(f2, h2.w, a.w);
        a.x = fmaf(f3, h3.x, a.x); a.y = fmaf(f3, h3.y, a.y);
        a.z = fmaf(f3, h3.z, a.z); a.w = fmaf(f3, h3.w, a.w);
    }
    for (; e < re; e++) {
        int2 we = g_ew[e];
        float wv = __int_as_float(we.y);
        float4 hv = *reinterpret_cast<const float4*>(h + (size_t)we.x * C + l * 4);
        a.x = fmaf(wv, hv.x, a.x); a.y = fmaf(wv, hv.y, a.y);
        a.z = fmaf(wv, hv.z, a.z); a.w = fmaf(wv, hv.w, a.w);
    }

    if (RELUB) {
        const float4 b = *reinterpret_cast<const float4*>(bias + l * 4);
        a.x = fmaxf(a.x + b.x, 0.f); a.y = fmaxf(a.y + b.y, 0.f);
        a.z = fmaxf(a.z + b.z, 0.f); a.w = fmaxf(a.w + b.w, 0.f);
    } else {
        const float* other = bufptr(othersel);
        float4 o = *reinterpret_cast<const float4*>(other + (size_t)node * C + l * 4);
        a.x += o.x; a.y += o.y; a.z += o.z; a.w += o.w;
    }
    *reinterpret_cast<float4*>(out + (size_t)node * C + l * 4) = a;
}

// ---------------- fused: h2 = relu(P(A)+b2) -> heads -> out ----------------
__global__ __launch_bounds__(256) void k_prop_heads(
    int hsel, const float* __restrict__ b2,
    const float* __restrict__ Wp1, const float* __restrict__ bp1,
    const float* __restrict__ Wp2, const float* __restrict__ bp2,
    const float* __restrict__ Wc1, const float* __restrict__ bc1,
    const float* __restrict__ Wc2, const float* __restrict__ bc2,
    float* __restrict__ out, int n)
{
    __shared__ float sWp1[32 * 32], sWp2[32 * 32], sWc1[32 * 16], sWc2[16 * 2];
    __shared__ float sbp1[32], sbp2[32], sbc1[16], sbc2[2];
    const int t = threadIdx.x;
    for (int i = t; i < 1024; i += 256) { sWp1[i] = Wp1[i]; sWp2[i] = Wp2[i]; }
    for (int i = t; i < 512; i += 256) sWc1[i] = Wc1[i];
    if (t < 32) { sWc2[t] = Wc2[t]; sbp1[t] = bp1[t]; sbp2[t] = bp2[t]; }
    if (t < 16) sbc1[t] = bc1[t];
    if (t < 2) sbc2[t] = bc2[t];
    __syncthreads();

    const float* h = bufptr(hsel);
    const int node = (blockIdx.x * blockDim.x + t) >> 5;
    const int lane = t & 31;
    if (node >= n) return;

    const float dv = g_dinv[node];
    const float sw = dv * dv;
    const int rs = g_rowptr[node];
    const int re = rs + g_cnt[node];

    float acc = sw * h[(size_t)node * 32 + lane];
    int e = rs;
    for (; e + 4 <= re; e += 4) {
        int2 w0 = g_ew[e], w1 = g_ew[e + 1], w2 = g_ew[e + 2], w3 = g_ew[e + 3];
        float h0 = h[(size_t)w0.x * 32 + lane];
        float h1 = h[(size_t)w1.x * 32 + lane];
        float h2v = h[(size_t)w2.x * 32 + lane];
        float h3 = h[(size_t)w3.x * 32 + lane];
        acc = fmaf(__int_as_float(w0.y), h0, acc);
        acc = fmaf(__int_as_float(w1.y), h1, acc);
        acc = fmaf(__int_as_float(w2.y), h2v, acc);
        acc = fmaf(__int_as_float(w3.y), h3, acc);
    }
    for (; e < re; e++) {
        int2 we = g_ew[e];
        acc = fmaf(__int_as_float(we.y), h[(size_t)we.x * 32 + lane], acc);
    }
    const float hv = fmaxf(acc + b2[lane], 0.f);

    float t1 = sbp1[lane];
#pragma unroll
    for (int k = 0; k < 32; k++)
        t1 = fmaf(__shfl_sync(0xffffffffu, hv, k), sWp1[k * 32 + lane], t1);
    t1 = fmaxf(t1, 0.f);

    float z = sbp2[lane];
#pragma unroll
    for (int k = 0; k < 32; k++)
        z = fmaf(__shfl_sync(0xffffffffu, t1, k), sWp2[k * 32 + lane], z);
    out[(size_t)n * 2 + (size_t)node * 32 + lane] = z;

    float tc = sbc1[lane & 15];
#pragma unroll
    for (int k = 0; k < 32; k++)
        tc = fmaf(__shfl_sync(0xffffffffu, hv, k), sWc1[k * 16 + (lane & 15)], tc);
    tc = fmaxf(tc, 0.f);

    float c0 = 0.f, c1 = 0.f;
#pragma unroll
    for (int k = 0; k < 16; k++) {
        float v = __shfl_sync(0xffffffffu, tc, k);
        c0 = fmaf(v, sWc2[k * 2 + 0], c0);
        c1 = fmaf(v, sWc2[k * 2 + 1], c1);
    }
    if (lane == 0) {
        out[(size_t)node * 2 + 0] = c0 + sbc2[0];
        out[(size_t)node * 2 + 1] = c1 + sbc2[1];
    }
}

// ---------------- launch ----------------
extern "C" void kernel_launch(void* const* d_in, const int* in_sizes, int n_in,
                              void* d_out, int out_size)
{
    const float* x  = (const float*)d_in[0];
    const int*   ei = (const int*)d_in[1];
    const float* W1_1 = (const float*)d_in[2];
    const float* W1_2 = (const float*)d_in[3];
    const float* b1   = (const float*)d_in[4];
    const float* W2_1 = (const float*)d_in[5];
    const float* W2_2 = (const float*)d_in[6];
    const float* b2   = (const float*)d_in[7];
    const float* Wp1  = (const float*)d_in[8];
    const float* bp1  = (const float*)d_in[9];
    const float* Wp2  = (const float*)d_in[10];
    const float* bp2  = (const float*)d_in[11];
    const float* Wc1  = (const float*)d_in[12];
    const float* bc1  = (const float*)d_in[13];
    const float* Wc2  = (const float*)d_in[14];
    const float* bc2  = (const float*)d_in[15];
    float* out = (float*)d_out;

    const int n = in_sizes[0] / 128;
    const int E = in_sizes[1] / 2;

    // fork: CSR build on g_s1, GEMM1 on main stream
    cudaEventRecord(g_ef, 0);
    cudaStreamWaitEvent(g_s1, g_ef, 0);

    const int n4 = (n + 3) / 4;
    k_zero   <<<(n4 + 255) / 256, 256, 0, g_s1>>>(n4);
    k_hist   <<<(E + 255) / 256, 256, 0, g_s1>>>(ei, E, n);
    k_scan   <<<1, 1024, 0, g_s1>>>(n);
    k_scatter<<<(E + 255) / 256, 256, 0, g_s1>>>(ei, E, n);
    cudaEventRecord(g_ej, g_s1);

    const int gb = (n + 127) / 128;
    k_gemm_dual<128, 128><<<gb, 256>>>(x, -1, W1_1, W1_2, 0, 1, n);

    // join
    cudaStreamWaitEvent(0, g_ej, 0);

    const int pb64 = (n * 16 + 255) / 256;
    const int pb32 = (n * 8 + 255) / 256;
    const int pbh  = (n + 7) / 8;

    k_prop<64, false><<<pb64, 256>>>(1, nullptr, 0, 2, n);  // C = P(B) + A
    k_prop<64, true ><<<pb64, 256>>>(2, b1, -1, 0, n);      // A = relu(P(C)+b1) = h1

    k_gemm_dual<64, 64><<<gb, 256>>>(nullptr, 0, W2_1, W2_2, 1, 2, n);
    k_prop<32, false><<<pb32, 256>>>(2, nullptr, 1, 0, n);  // A = P(C) + B

    k_prop_heads<<<pbh, 256>>>(0, b2, Wp1, bp1, Wp2, bp2, Wc1, bc1, Wc2, bc2, out, n);
}